// round 14
// baseline (speedup 1.0000x reference)
#include <cuda_runtime.h>
#include <cuda_bf16.h>
#include <math_constants.h>
#include <cstdint>

#define NPIX 4096
#define CCH  256
#define HEADS 4
#define DH   64

// ---------------- bf16 helpers ----------------
__device__ __forceinline__ uint32_t pkbf2(__nv_bfloat16 a, __nv_bfloat16 b) {
    __nv_bfloat162 t = __halves2bfloat162(a, b);
    return *reinterpret_cast<uint32_t*>(&t);
}
__device__ __forceinline__ void bsplit(float v, __nv_bfloat16 &h, __nv_bfloat16 &l) {
    h = __float2bfloat16(v);
    l = __float2bfloat16(v - __bfloat162float(h));
}

__device__ __forceinline__ void mma16816(float c[4], const uint32_t a[4],
                                         uint32_t b0, uint32_t b1) {
    asm volatile("mma.sync.aligned.m16n8k16.row.col.f32.bf16.bf16.f32 "
        "{%0,%1,%2,%3}, {%4,%5,%6,%7}, {%8,%9}, {%0,%1,%2,%3};"
        : "+f"(c[0]), "+f"(c[1]), "+f"(c[2]), "+f"(c[3])
        : "r"(a[0]), "r"(a[1]), "r"(a[2]), "r"(a[3]), "r"(b0), "r"(b1));
}
__device__ __forceinline__ void ldsm_x4(uint32_t r[4], uint32_t addr) {
    asm volatile("ldmatrix.sync.aligned.m8n8.x4.shared.b16 {%0,%1,%2,%3}, [%4];"
        : "=r"(r[0]), "=r"(r[1]), "=r"(r[2]), "=r"(r[3]) : "r"(addr));
}
__device__ __forceinline__ void ldsm_x4t(uint32_t r[4], uint32_t addr) {
    asm volatile("ldmatrix.sync.aligned.m8n8.x4.trans.shared.b16 {%0,%1,%2,%3}, [%4];"
        : "=r"(r[0]), "=r"(r[1]), "=r"(r[2]), "=r"(r[3]) : "r"(addr));
}
__device__ __forceinline__ void cp_async16(uint32_t dst, const void* src) {
    asm volatile("cp.async.cg.shared.global [%0], [%1], 16;" :: "r"(dst), "l"(src));
}
#define CP_COMMIT() asm volatile("cp.async.commit_group;" ::: "memory")
#define CP_WAIT1()  asm volatile("cp.async.wait_group 1;" ::: "memory")
#define CP_WAIT0()  asm volatile("cp.async.wait_group 0;" ::: "memory")

__device__ __forceinline__ uint32_t smem_u32(const void* p) {
    uint32_t a;
    asm("{ .reg .u64 t; cvta.to.shared.u64 t, %1; cvt.u32.u64 %0, t; }"
        : "=r"(a) : "l"(p));
    return a;
}
__device__ __forceinline__ float ex2(float x) {
    float r; asm("ex2.approx.f32 %0, %1;" : "=f"(r) : "f"(x)); return r;
}
__device__ __forceinline__ uint32_t cvt_bf2(float lo, float hi) {
    uint32_t r; asm("cvt.rn.bf16x2.f32 %0, %1, %2;" : "=r"(r) : "f"(hi), "f"(lo));
    return r;
}

#define SW_OFF(row, chunk) ((((uint32_t)(row)) << 7) + (((uint32_t)((chunk) ^ ((row) & 7))) << 4))

#define QSCALE 0.1803368801111204f   /* 0.125 * log2(e) */

// ---------------- scratch globals ----------------
__device__ __align__(16) __nv_bfloat16 g_xh[2 * CCH * NPIX];
__device__ __align__(16) __nv_bfloat16 g_xl[2 * CCH * NPIX];
__device__ __align__(16) __nv_bfloat16 g_weh[HEADS * 192 * CCH];
__device__ __align__(16) __nv_bfloat16 g_wel[HEADS * 192 * CCH];
__device__ __align__(16) __nv_bfloat16 g_woh[CCH * CCH];
__device__ __align__(16) __nv_bfloat16 g_wol[CCH * CCH];
__device__ __align__(16) __nv_bfloat16 g_qh[8 * DH * NPIX];   // [bh][d][n]
__device__ __align__(16) __nv_bfloat16 g_ql[8 * DH * NPIX];
__device__ __align__(16) __nv_bfloat16 g_kh[8 * DH * NPIX];
__device__ __align__(16) __nv_bfloat16 g_kl[8 * DH * NPIX];
__device__ __align__(16) __nv_bfloat16 g_vh[8 * DH * NPIX];
__device__ __align__(16) __nv_bfloat16 g_vl[8 * DH * NPIX];
__device__ __align__(16) __nv_bfloat16 g_yh[2 * CCH * NPIX];  // [b][k][n]
__device__ __align__(16) __nv_bfloat16 g_yl[2 * CCH * NPIX];

// ===========================================================================
// Kernel 0: fused fp32 -> split bf16 for x, w_embed, w_out  (one launch)
// ===========================================================================
__global__ __launch_bounds__(256) void k_split_all(const float* __restrict__ x,
                                                   const float* __restrict__ w_embed,
                                                   const float* __restrict__ w_out)
{
    int i = blockIdx.x * 256 + threadIdx.x;
    const float* src;
    __nv_bfloat16 *dh, *dl;
    int j;
    if (i < 524288)       { src = x;       dh = g_xh;  dl = g_xl;  j = i; }
    else if (i < 573440)  { src = w_embed; dh = g_weh; dl = g_wel; j = i - 524288; }
    else                  { src = w_out;   dh = g_woh; dl = g_wol; j = i - 573440; }
    float4 v = ((const float4*)src)[j];
    __nv_bfloat16 h0,l0,h1,l1,h2,l2,h3,l3;
    bsplit(v.x,h0,l0); bsplit(v.y,h1,l1); bsplit(v.z,h2,l2); bsplit(v.w,h3,l3);
    ((uint2*)dh)[j] = make_uint2(pkbf2(h0,h1), pkbf2(h2,h3));
    ((uint2*)dl)[j] = make_uint2(pkbf2(l0,l1), pkbf2(l2,l3));
}

// ===========================================================================
// Kernel 1: QKV 1x1 conv via mma.sync, n-tile 64, dist-2 (round-8 measured best)
// ===========================================================================
__global__ __launch_bounds__(128) void k_qkv(const float* __restrict__ b_embed)
{
    __shared__ __align__(16) char sm[3 * 10240];
    const uint32_t sb = smem_u32(sm);

    const int t    = threadIdx.x;
    const int lane = t & 31;
    const int w    = t >> 5;
    const int gid  = lane >> 2;
    const int tg   = lane & 3;

    const int bh = blockIdx.z;
    const int h  = bh & 3;
    const int b  = bh >> 2;
    const int y  = blockIdx.y;
    const int mb = y * 64;
    const int nb = blockIdx.x * 64;

    const __nv_bfloat16* Wh = g_weh + (size_t)(h * 192 + mb) * CCH;
    const __nv_bfloat16* Wl = g_wel + (size_t)(h * 192 + mb) * CCH;
    const __nv_bfloat16* Xh = g_xh + (size_t)b * CCH * NPIX + nb;
    const __nv_bfloat16* Xl = g_xl + (size_t)b * CCH * NPIX + nb;

    const int fm = t >> 1, fch2 = t & 1;
    const int fc = t >> 3, fch = t & 7;
    const uint32_t xoff = SW_OFF(fc, fch);

    const uint32_t a_m   = 16 * w + (lane & 7) + ((lane >> 3) & 1) * 8;
    const uint32_t a_off = a_m * 48 + (lane >> 4) * 16;
    const uint32_t b_row = (lane & 7) + ((lane >> 3) & 1) * 8;
    const uint32_t b_ch  = lane >> 4;

    float c[8][4] = {};

    #pragma unroll
    for (int s0 = 0; s0 < 2; s0++) {
        const uint32_t st = sb + (uint32_t)s0 * 10240;
        const int c0 = s0 * 16;
        cp_async16(st + fm * 48 + fch2 * 16,        Wh + fm * CCH + c0 + fch2 * 8);
        cp_async16(st + 3072 + fm * 48 + fch2 * 16, Wl + fm * CCH + c0 + fch2 * 8);
        cp_async16(st + 6144 + xoff, Xh + (size_t)(c0 + fc) * NPIX + fch * 8);
        cp_async16(st + 8192 + xoff, Xl + (size_t)(c0 + fc) * NPIX + fch * 8);
        CP_COMMIT();
    }

    for (int s = 0; s < 16; s++) {
        CP_WAIT1();
        __syncthreads();
        if (s + 2 < 16) {
            const uint32_t st = sb + (uint32_t)((s + 2) % 3) * 10240;
            const int c0 = (s + 2) * 16;
            cp_async16(st + fm * 48 + fch2 * 16,        Wh + fm * CCH + c0 + fch2 * 8);
            cp_async16(st + 3072 + fm * 48 + fch2 * 16, Wl + fm * CCH + c0 + fch2 * 8);
            cp_async16(st + 6144 + xoff, Xh + (size_t)(c0 + fc) * NPIX + fch * 8);
            cp_async16(st + 8192 + xoff, Xl + (size_t)(c0 + fc) * NPIX + fch * 8);
        }
        CP_COMMIT();

        const uint32_t st = sb + (uint32_t)(s % 3) * 10240;
        uint32_t ah[4], al[4];
        ldsm_x4(ah, st + a_off);
        ldsm_x4(al, st + 3072 + a_off);
        #pragma unroll
        for (int ng = 0; ng < 4; ng++) {
            const uint32_t off = (b_row << 7) + ((((2 * ng + b_ch)) ^ (lane & 7)) << 4);
            uint32_t bh4[4], bl4[4];
            ldsm_x4t(bh4, st + 6144 + off);
            ldsm_x4t(bl4, st + 8192 + off);
            mma16816(c[2*ng],   ah, bh4[0], bh4[1]);
            mma16816(c[2*ng+1], ah, bh4[2], bh4[3]);
            mma16816(c[2*ng],   ah, bl4[0], bl4[1]);
            mma16816(c[2*ng+1], ah, bl4[2], bl4[3]);
            mma16816(c[2*ng],   al, bh4[0], bh4[1]);
            mma16816(c[2*ng+1], al, bh4[2], bh4[3]);
        }
    }

    const float biasg  = b_embed[h * 192 + mb + 16 * w + gid];
    const float biasg8 = b_embed[h * 192 + mb + 16 * w + gid + 8];
    const float sc = (y == 0) ? QSCALE : 1.0f;
    __nv_bfloat16 *dh, *dl;
    if (y == 0)      { dh = g_qh; dl = g_ql; }
    else if (y == 1) { dh = g_kh; dl = g_kl; }
    else             { dh = g_vh; dl = g_vl; }
    const size_t baseg  = ((size_t)bh * 64 + 16 * w + gid) * NPIX + nb;
    const size_t baseg8 = baseg + (size_t)8 * NPIX;

    #pragma unroll
    for (int blk = 0; blk < 8; blk++) {
        const int n = 8 * blk + 2 * tg;
        float v0 = (c[blk][0] + biasg)  * sc;
        float v1 = (c[blk][1] + biasg)  * sc;
        float v2 = (c[blk][2] + biasg8) * sc;
        float v3 = (c[blk][3] + biasg8) * sc;
        __nv_bfloat16 h0,l0,h1,l1,h2,l2,h3,l3;
        bsplit(v0,h0,l0); bsplit(v1,h1,l1); bsplit(v2,h2,l2); bsplit(v3,h3,l3);
        *(uint32_t*)(dh + baseg  + n) = pkbf2(h0, h1);
        *(uint32_t*)(dl + baseg  + n) = pkbf2(l0, l1);
        *(uint32_t*)(dh + baseg8 + n) = pkbf2(h2, h3);
        *(uint32_t*)(dl + baseg8 + n) = pkbf2(l2, l3);
    }
}

// ===========================================================================
// Kernel 2: flash attention, 3-stage ring (96KB), dist-1 prefetch,
// PV delayed 1 tile, 2 CTAs/SM (__launch_bounds__(256,2))
// grid (32 i-tiles, 4 heads, 2 batch), block 256
// ===========================================================================
#define TILE_BYTES 32768

#define PREFETCH_TILE(jn) do {                                                  \
    if ((jn) < 64) {                                                            \
        const uint32_t pb_ = sb + ((uint32_t)((jn) % 3)) * TILE_BYTES;          \
        const int jnn_ = (jn) << 6;                                             \
        const size_t o0_ = (size_t)f0row * NPIX + jnn_ + f0c * 8;               \
        const size_t o1_ = (size_t)f1row * NPIX + jnn_ + f1c * 8;               \
        cp_async16(pb_ + 0     + sw0, Kh + o0_);                                \
        cp_async16(pb_ + 0     + sw1, Kh + o1_);                                \
        cp_async16(pb_ + 8192  + sw0, Kl + o0_);                                \
        cp_async16(pb_ + 8192  + sw1, Kl + o1_);                                \
        cp_async16(pb_ + 16384 + sw0, Vh + o0_);                                \
        cp_async16(pb_ + 16384 + sw1, Vh + o1_);                                \
        cp_async16(pb_ + 24576 + sw0, Vl + o0_);                                \
        cp_async16(pb_ + 24576 + sw1, Vl + o1_);                                \
    }                                                                           \
} while (0)

#define ATTN_ITER(JT, CH, CL, PH, PL, DOPV) do {                                \
    __syncthreads();    /* slot (JT+1)%3 free: tile JT-2 fully consumed */      \
    PREFETCH_TILE((JT) + 1);                                                    \
    CP_COMMIT();                                                                \
    CP_WAIT1();         /* tile JT arrived */                                   \
    __syncthreads();                                                            \
    const uint32_t tb_ = sb + ((uint32_t)((JT) % 3)) * TILE_BYTES;              \
    const uint32_t vp_ = sb + ((uint32_t)(((JT) + 2) % 3)) * TILE_BYTES + 16384;\
    _Pragma("unroll")                                                           \
    for (int nn_ = 0; nn_ < 8; nn_++) { s[nn_][0]=0; s[nn_][1]=0; s[nn_][2]=0; s[nn_][3]=0; } \
    _Pragma("unroll")                                                           \
    for (int jg_ = 0; jg_ < 4; jg_++) {                                         \
        _Pragma("unroll")                                                       \
        for (int kk_ = 0; kk_ < 4; kk_++) {                                     \
            const uint32_t row_ = 16 * kk_ + kdl;                               \
            const uint32_t off_ = (row_ << 7) + (((2 * jg_ + kch) ^ (lane & 7)) << 4); \
            uint32_t bh4_[4], bl4_[4];                                          \
            ldsm_x4t(bh4_, tb_ + off_);                                         \
            ldsm_x4t(bl4_, tb_ + 8192 + off_);                                  \
            mma16816(s[2*jg_],   qh[kk_], bh4_[0], bh4_[1]);                    \
            mma16816(s[2*jg_+1], qh[kk_], bh4_[2], bh4_[3]);                    \
            mma16816(s[2*jg_],   qh[kk_], bl4_[0], bl4_[1]);                    \
            mma16816(s[2*jg_+1], qh[kk_], bl4_[2], bl4_[3]);                    \
            mma16816(s[2*jg_],   ql[kk_], bh4_[0], bh4_[1]);                    \
            mma16816(s[2*jg_+1], ql[kk_], bh4_[2], bh4_[3]);                    \
        }                                                                       \
    }                                                                           \
    _Pragma("unroll")                                                           \
    for (int nn_ = 0; nn_ < 8; nn_++) {                                         \
        const float p0_ = ex2(s[nn_][0]);                                       \
        const float p1_ = ex2(s[nn_][1]);                                       \
        const float p2_ = ex2(s[nn_][2]);                                       \
        const float p3_ = ex2(s[nn_][3]);                                       \
        rs_lo += p0_ + p1_;                                                     \
        rs_hi += p2_ + p3_;                                                     \
        const uint32_t h01_ = cvt_bf2(p0_, p1_);                                \
        const uint32_t h23_ = cvt_bf2(p2_, p3_);                                \
        const float r0_ = p0_ - __uint_as_float(h01_ << 16);                    \
        const float r1_ = p1_ - __uint_as_float(h01_ & 0xFFFF0000u);            \
        const float r2_ = p2_ - __uint_as_float(h23_ << 16);                    \
        const float r3_ = p3_ - __uint_as_float(h23_ & 0xFFFF0000u);            \
        CH[nn_ >> 1][((nn_ & 1) << 1) + 0] = h01_;                              \
        CH[nn_ >> 1][((nn_ & 1) << 1) + 1] = h23_;                              \
        CL[nn_ >> 1][((nn_ & 1) << 1) + 0] = cvt_bf2(r0_, r1_);                 \
        CL[nn_ >> 1][((nn_ & 1) << 1) + 1] = cvt_bf2(r2_, r3_);                 \
        if (DOPV) {                                                             \
            const uint32_t vb_ = vp_ + (uint32_t)nn_ * 1024;                    \
            uint32_t vh4_[4], vl4_[4];                                          \
            ldsm_x4(vh4_, vb_ + frag0);                                         \
            ldsm_x4(vl4_, vb_ + 8192 + frag0);                                  \
            mma16816(o[nn_], PH[0], vh4_[0], vh4_[1]);                          \
            mma16816(o[nn_], PH[1], vh4_[2], vh4_[3]);                          \
            mma16816(o[nn_], PH[0], vl4_[0], vl4_[1]);                          \
            mma16816(o[nn_], PH[1], vl4_[2], vl4_[3]);                          \
            mma16816(o[nn_], PL[0], vh4_[0], vh4_[1]);                          \
            mma16816(o[nn_], PL[1], vh4_[2], vh4_[3]);                          \
            ldsm_x4(vh4_, vb_ + frag1);                                         \
            ldsm_x4(vl4_, vb_ + 8192 + frag1);                                  \
            mma16816(o[nn_], PH[2], vh4_[0], vh4_[1]);                          \
            mma16816(o[nn_], PH[3], vh4_[2], vh4_[3]);                          \
            mma16816(o[nn_], PH[2], vl4_[0], vl4_[1]);                          \
            mma16816(o[nn_], PH[3], vl4_[2], vl4_[3]);                          \
            mma16816(o[nn_], PL[2], vh4_[0], vh4_[1]);                          \
            mma16816(o[nn_], PL[3], vh4_[2], vh4_[3]);                          \
        }                                                                       \
    }                                                                           \
} while (0)

__global__ void __launch_bounds__(256, 2) k_attn()
{
    extern __shared__ char dynsm_raw[];
    char* dynsm = (char*)(((uintptr_t)dynsm_raw + 127) & ~(uintptr_t)127);
    const uint32_t sb = smem_u32(dynsm);

    const int tid  = threadIdx.x;
    const int lane = tid & 31;
    const int wid  = tid >> 5;
    const int gid  = lane >> 2;
    const int tg   = lane & 3;

    const int b  = blockIdx.z;
    const int h  = blockIdx.y;
    const int bh = b * HEADS + h;
    const int ib = blockIdx.x * 128;
    const int r0 = wid * 16;

    const __nv_bfloat16* Qh = g_qh + (size_t)bh * DH * NPIX;
    const __nv_bfloat16* Ql = g_ql + (size_t)bh * DH * NPIX;
    const __nv_bfloat16* Kh = g_kh + (size_t)bh * DH * NPIX;
    const __nv_bfloat16* Kl = g_kl + (size_t)bh * DH * NPIX;
    const __nv_bfloat16* Vh = g_vh + (size_t)bh * DH * NPIX;
    const __nv_bfloat16* Vl = g_vl + (size_t)bh * DH * NPIX;

    // ---- stage Q [d64][i128] into slots 0/1 memory (consumed before ring use)
    #pragma unroll
    for (int r = 0; r < 8; r++) {
        const int s2   = tid + (r << 8);
        const int arr  = s2 >> 10;
        const int rem  = s2 & 1023;
        const int hf   = rem >> 9;
        const int rem2 = rem & 511;
        const int dr   = rem2 >> 3, ch = rem2 & 7;
        const uint32_t dst = sb + (uint32_t)arr * 16384 + (uint32_t)hf * 8192 + SW_OFF(dr, ch);
        const __nv_bfloat16* src = (arr ? Ql : Qh) + (size_t)dr * NPIX + ib + hf * 64 + ch * 8;
        cp_async16(dst, src);
    }
    CP_COMMIT();
    CP_WAIT0();
    __syncthreads();

    uint32_t qh[4][4], ql[4][4];
    {
        const int half = wid >> 2, w4 = wid & 3;
        const uint32_t arow = (lane & 7) + ((lane >> 4) << 3);
        const uint32_t ach  = 2 * w4 + ((lane >> 3) & 1);
        #pragma unroll
        for (int kk = 0; kk < 4; kk++) {
            const uint32_t row = 16 * kk + arow;
            const uint32_t off = (row << 7) + ((ach ^ (lane & 7)) << 4);
            ldsm_x4t(qh[kk], sb + (uint32_t)half * 8192 + off);
            ldsm_x4t(ql[kk], sb + 16384 + (uint32_t)half * 8192 + off);
        }
    }
    __syncthreads();

    const int f0row = tid >> 3,         f0c = tid & 7;
    const int f1row = (tid + 256) >> 3, f1c = tid & 7;
    const uint32_t sw0 = SW_OFF(f0row, f0c);
    const uint32_t sw1 = SW_OFF(f1row, f1c);

    const uint32_t kdl = (lane & 7) + ((lane >> 3) & 1) * 8;
    const uint32_t kch = lane >> 4;
    const uint32_t frag0 = ((uint32_t)(lane & 7) << 7) + ((uint32_t)(((lane >> 3) + 0) ^ (lane & 7)) << 4);
    const uint32_t frag1 = ((uint32_t)(lane & 7) << 7) + ((uint32_t)(((lane >> 3) + 4) ^ (lane & 7)) << 4);

    PREFETCH_TILE(0);
    CP_COMMIT();

    float o[8][4] = {};
    float s[8][4];
    float rs_lo = 0.0f, rs_hi = 0.0f;
    uint32_t pAh[4][4], pAl[4][4], pBh[4][4], pBl[4][4];

    { ATTN_ITER(0, pAh, pAl, pBh, pBl, 0); }
    for (int u = 0; u < 31; u++) {
        const int jt = 1 + 2 * u;
        { ATTN_ITER(jt,     pBh, pBl, pAh, pAl, 1); }
        { ATTN_ITER(jt + 1, pAh, pAl, pBh, pBl, 1); }
    }
    { ATTN_ITER(63, pBh, pBl, pAh, pAl, 1); }

    // drain: PV(63); V(63) lives in slot 63 % 3 == 0
    {
        const uint32_t vp = sb + 0u * TILE_BYTES + 16384;
        #pragma unroll
        for (int nn = 0; nn < 8; nn++) {
            const uint32_t vb = vp + (uint32_t)nn * 1024;
            uint32_t vh4[4], vl4[4];
            ldsm_x4(vh4, vb + frag0);
            ldsm_x4(vl4, vb + 8192 + frag0);
            mma16816(o[nn], pBh[0], vh4[0], vh4[1]);
            mma16816(o[nn], pBh[1], vh4[2], vh4[3]);
            mma16816(o[nn], pBh[0], vl4[0], vl4[1]);
            mma16816(o[nn], pBh[1], vl4[2], vl4[3]);
            mma16816(o[nn], pBl[0], vh4[0], vh4[1]);
            mma16816(o[nn], pBl[1], vh4[2], vh4[3]);
            ldsm_x4(vh4, vb + frag1);
            ldsm_x4(vl4, vb + 8192 + frag1);
            mma16816(o[nn], pBh[2], vh4[0], vh4[1]);
            mma16816(o[nn], pBh[3], vh4[2], vh4[3]);
            mma16816(o[nn], pBh[2], vl4[0], vl4[1]);
            mma16816(o[nn], pBh[3], vl4[2], vl4[3]);
            mma16816(o[nn], pBl[2], vh4[0], vh4[1]);
            mma16816(o[nn], pBl[3], vh4[2], vh4[3]);
        }
    }

    rs_lo += __shfl_xor_sync(0xffffffffu, rs_lo, 1);
    rs_lo += __shfl_xor_sync(0xffffffffu, rs_lo, 2);
    rs_hi += __shfl_xor_sync(0xffffffffu, rs_hi, 1);
    rs_hi += __shfl_xor_sync(0xffffffffu, rs_hi, 2);
    const float inv_lo = 1.0f / rs_lo;
    const float inv_hi = 1.0f / rs_hi;

    __syncthreads();
    float* osm = (float*)dynsm;            // [64][129] = 33KB, fits in ring
    #pragma unroll
    for (int nn = 0; nn < 8; nn++) {
        const int d0 = 8 * nn + 2 * tg;
        osm[(d0    ) * 129 + r0 + gid    ] = o[nn][0] * inv_lo;
        osm[(d0 + 1) * 129 + r0 + gid    ] = o[nn][1] * inv_lo;
        osm[(d0    ) * 129 + r0 + gid + 8] = o[nn][2] * inv_hi;
        osm[(d0 + 1) * 129 + r0 + gid + 8] = o[nn][3] * inv_hi;
    }
    __syncthreads();

    {
        const int d  = tid >> 2;
        const int ic = (tid & 3) * 8;
        const size_t gb = ((size_t)b * CCH + h * DH + d) * NPIX + ib;
        #pragma unroll
        for (int u = 0; u < 4; u++) {
            const int i = ic + u * 32;
            float v[8];
            #pragma unroll
            for (int k2 = 0; k2 < 8; k2++) v[k2] = osm[d * 129 + i + k2];
            uint32_t hw[4], lw[4];
            #pragma unroll
            for (int p = 0; p < 4; p++) {
                __nv_bfloat16 ha,la,hb,lb;
                bsplit(v[2*p],   ha, la);
                bsplit(v[2*p+1], hb, lb);
                hw[p] = pkbf2(ha, hb);
                lw[p] = pkbf2(la, lb);
            }
            *(uint4*)(g_yh + gb + i) = make_uint4(hw[0], hw[1], hw[2], hw[3]);
            *(uint4*)(g_yl + gb + i) = make_uint4(lw[0], lw[1], lw[2], lw[3]);
        }
    }
}

// ===========================================================================
// Kernel 3: output 1x1 conv + bias + residual, n-tile 64, dist-2
// ===========================================================================
__global__ __launch_bounds__(128) void k_out(const float* __restrict__ x,
                                             const float* __restrict__ b_out,
                                             float* __restrict__ out)
{
    __shared__ __align__(16) char sm[3 * 8192];
    const uint32_t sb = smem_u32(sm);

    const int t    = threadIdx.x;
    const int lane = t & 31;
    const int w    = t >> 5;
    const int gid  = lane >> 2;
    const int tg   = lane & 3;

    const int b  = blockIdx.z;
    const int cb = blockIdx.y * 64;
    const int nb = blockIdx.x * 64;

    const __nv_bfloat16* Yh = g_yh + (size_t)b * CCH * NPIX + nb;
    const __nv_bfloat16* Yl = g_yl + (size_t)b * CCH * NPIX + nb;

    const int fk = t >> 3, fch = t & 7;
    const uint32_t foff = SW_OFF(fk, fch);

    const uint32_t arow = (lane & 7) + ((lane >> 4) << 3);
    const uint32_t ach  = 2 * w + ((lane >> 3) & 1);
    const uint32_t aoff = (arow << 7) + ((ach ^ (lane & 7)) << 4);
    const uint32_t brow = (lane & 7) + ((lane >> 3) & 1) * 8;
    const uint32_t bch  = lane >> 4;

    float c[8][4] = {};

    #pragma unroll
    for (int s0 = 0; s0 < 2; s0++) {
        const uint32_t st = sb + (uint32_t)s0 * 8192;
        const int k0 = s0 * 16;
        cp_async16(st + foff,        g_woh + (size_t)(k0 + fk) * CCH + cb + fch * 8);
        cp_async16(st + 2048 + foff, g_wol + (size_t)(k0 + fk) * CCH + cb + fch * 8);
        cp_async16(st + 4096 + foff, Yh + (size_t)(k0 + fk) * NPIX + fch * 8);
        cp_async16(st + 6144 + foff, Yl + (size_t)(k0 + fk) * NPIX + fch * 8);
        CP_COMMIT();
    }

    for (int s = 0; s < 16; s++) {
        CP_WAIT1();
        __syncthreads();
        if (s + 2 < 16) {
            const uint32_t st = sb + (uint32_t)((s + 2) % 3) * 8192;
            const int k0 = (s + 2) * 16;
            cp_async16(st + foff,        g_woh + (size_t)(k0 + fk) * CCH + cb + fch * 8);
            cp_async16(st + 2048 + foff, g_wol + (size_t)(k0 + fk) * CCH + cb + fch * 8);
            cp_async16(st + 4096 + foff, Yh + (size_t)(k0 + fk) * NPIX + fch * 8);
            cp_async16(st + 6144 + foff, Yl + (size_t)(k0 + fk) * NPIX + fch * 8);
        }
        CP_COMMIT();

        const uint32_t st = sb + (uint32_t)(s % 3) * 8192;
        uint32_t ah[4], al[4];
        ldsm_x4t(ah, st + aoff);
        ldsm_x4t(al, st + 2048 + aoff);
        #pragma unroll
        for (int ng = 0; ng < 4; ng++) {
            const uint32_t off = (brow << 7) + (((2 * ng + bch) ^ (lane & 7)) << 4);
            uint32_t bh4[4], bl4[4];
            ldsm_x4t(bh4, st + 4096 + off);
            ldsm_x4t(bl4, st + 6144 + off);
            mma16816(c[2*ng],   ah, bh4[0], bh4[1]);
            mma16816(c[2*ng+1], ah, bh4[2], bh4[3]);
            mma16816(c[2*ng],   ah, bl4[0], bl4[1]);
            mma16816(c[2*ng+1], ah, bl4[2], bl4[3]);
            mma16816(c[2*ng],   al, bh4[0], bh4[1]);
            mma16816(c[2*ng+1], al, bh4[2], bh4[3]);
        }
    }

    const int cw = cb + 16 * w + gid;
    const float bias0 = b_out[cw];
    const float bias8 = b_out[cw + 8];
    const size_t off0 = ((size_t)(b * CCH + cw)) * NPIX + nb;
    const size_t off8 = off0 + (size_t)8 * NPIX;

    #pragma unroll
    for (int blk = 0; blk < 8; blk++) {
        const int n = 8 * blk + 2 * tg;
        const float2 x0 = *(const float2*)(x + off0 + n);
        const float2 x8 = *(const float2*)(x + off8 + n);
        *(float2*)(out + off0 + n) = make_float2(c[blk][0] + bias0 + x0.x,
                                                 c[blk][1] + bias0 + x0.y);
        *(float2*)(out + off8 + n) = make_float2(c[blk][2] + bias8 + x8.x,
                                                 c[blk][3] + bias8 + x8.y);
    }
}

// ===========================================================================
extern "C" void kernel_launch(void* const* d_in, const int* in_sizes, int n_in,
                              void* d_out, int out_size)
{
    const float* x       = (const float*)d_in[0];
    const float* w_embed = (const float*)d_in[1];
    const float* b_embed = (const float*)d_in[2];
    const float* w_out   = (const float*)d_in[3];
    const float* b_out   = (const float*)d_in[4];
    float* out = (float*)d_out;

    static int smem_set = 0;
    if (!smem_set) {
        cudaFuncSetAttribute(k_attn, cudaFuncAttributeMaxDynamicSharedMemorySize,
                             3 * TILE_BYTES + 128);
        smem_set = 1;
    }

    k_split_all<<<2304, 256>>>(x, w_embed, w_out);
    k_qkv<<<dim3(64, 3, 8), 128>>>(b_embed);
    k_attn<<<dim3(32, HEADS, 2), 256, 3 * TILE_BYTES + 128>>>();
    k_out<<<dim3(64, 4, 2), 128>>>(x, b_out, out);
}